// round 10
// baseline (speedup 1.0000x reference)
#include <cuda_runtime.h>
#include <cstdint>

#define HIDDEN    1024
#define MOE_FF    512
#define SHARED_FF 2816
#define NE        16
#define NTOK      2048
#define NENT      (2*NTOK)

// ---------------- scratch (device globals; no allocation allowed) ----------
__device__ float g_H1[NTOK * SHARED_FF];     // shared-expert hidden (tf32-rounded)
__device__ float g_Hx[NENT * MOE_FF];        // expert hidden per entry (tf32-rounded)
__device__ float g_partial[NENT * HIDDEN];   // weighted expert out per entry
__device__ int   g_list[NE][NTOK];           // entry id (2n+k) per expert bucket
__device__ int   g_cnt[NE];
__device__ float g_wts[NENT];                // renormalized router weight per entry
__device__ float g_sig[NTOK];                // shared-expert sigmoid gate

__device__ __forceinline__ float silu_f(float v) { return v / (1.f + __expf(-v)); }
__device__ __forceinline__ float to_tf32(float x) {
    float y; asm("cvt.rna.tf32.f32 %0, %1;" : "=f"(y) : "f"(x)); return y;
}

// m16n8k8 TF32 HMMA (generic PTX — valid on target sm_103)
__device__ __forceinline__ void mma8(float* c, const uint32_t* a, const uint32_t* b) {
    asm volatile(
        "mma.sync.aligned.m16n8k8.row.col.f32.tf32.tf32.f32 "
        "{%0,%1,%2,%3}, {%4,%5,%6,%7}, {%8,%9}, {%0,%1,%2,%3};"
        : "+f"(c[0]), "+f"(c[1]), "+f"(c[2]), "+f"(c[3])
        : "r"(a[0]), "r"(a[1]), "r"(a[2]), "r"(a[3]), "r"(b[0]), "r"(b[1]));
}

__device__ __forceinline__ uint32_t smem_u32(const void* p) {
    uint32_t a;
    asm("{ .reg .u64 t; cvta.to.shared.u64 t, %1; cvt.u32.u64 %0, t; }" : "=r"(a) : "l"(p));
    return a;
}
#define CP_ASYNC16(dst, src) \
    asm volatile("cp.async.cg.shared.global [%0], [%1], 16;" :: "r"(dst), "l"(src))
#define CP_COMMIT() asm volatile("cp.async.commit_group;" ::: "memory")
#define CP_WAIT(n)  asm volatile("cp.async.wait_group %0;" :: "n"(n) : "memory")

// ---------------- misc ------------------------------------------------------
__global__ void k_zero_cnt() {
    if (threadIdx.x < NE) g_cnt[threadIdx.x] = 0;
}

// ---------------- router: logits -> top2 -> renorm weights + buckets --------
__global__ void k_router(const float* __restrict__ x,
                         const float* __restrict__ gw,
                         const float* __restrict__ sgw) {
    int n = blockIdx.x;
    int t = threadIdx.x;
    float xv[8];
#pragma unroll
    for (int i = 0; i < 8; i++) xv[i] = x[n * HIDDEN + t + i * 128];

    __shared__ float red[17 * 4];
    for (int e = 0; e < 17; e++) {
        const float* wr = (e < 16) ? (gw + e * HIDDEN) : sgw;
        float s = 0.f;
#pragma unroll
        for (int i = 0; i < 8; i++) s += xv[i] * wr[t + i * 128];
#pragma unroll
        for (int o = 16; o; o >>= 1) s += __shfl_xor_sync(0xffffffffu, s, o);
        if ((t & 31) == 0) red[e * 4 + (t >> 5)] = s;
    }
    __syncthreads();
    if (t == 0) {
        float lg[17];
        for (int e = 0; e < 17; e++)
            lg[e] = red[e * 4] + red[e * 4 + 1] + red[e * 4 + 2] + red[e * 4 + 3];
        int i0 = 0;
        for (int e = 1; e < 16; e++) if (lg[e] > lg[i0]) i0 = e;
        int i1 = -1;
        for (int e = 0; e < 16; e++) {
            if (e == i0) continue;
            if (i1 < 0 || lg[e] > lg[i1]) i1 = e;
        }
        float m  = lg[i0];
        float e0 = expf(lg[i0] - m);
        float e1 = expf(lg[i1] - m);
        float inv = 1.f / (e0 + e1);
        g_wts[2 * n]     = e0 * inv;
        g_wts[2 * n + 1] = e1 * inv;
        int p0 = atomicAdd(&g_cnt[i0], 1); g_list[i0][p0] = 2 * n;
        int p1 = atomicAdd(&g_cnt[i1], 1); g_list[i1][p1] = 2 * n + 1;
        g_sig[n] = 1.f / (1.f + expf(-lg[16]));
    }
}

// ---------------- TF32 HMMA GEMM, 3-stage cp.async ring ---------------------
// DUAL  modes (0,2): CTA 128x64,  8 warps 4Mx2N, warp 32x32 (acc 32+32).
//                    1.5 LDS/MMA already (A shared by both B streams).
// SINGLE modes (1,3): CTA 128x128, 8 warps 4Mx2N, warp 32x64 (acc 64).
//                    1.5 LDS/MMA (was 2.0) -> LDS-bound ceiling 33%->67%.
// A smem [m][k] LDA=36. B smem: modes 0/1 [n][k] LDA=36; modes 2/3 [k][n]
// LDN = 72 (dual) / 136 (single). All fragment LDS conflict-free
// (bank index = 4g+tg resp. 8tg+g spans 0..31).
template<int KTOT, bool DUAL, int MODE>
__global__ void __launch_bounds__(256, 2)
k_mma(const float* __restrict__ Ag, const float* __restrict__ Bg,
      const float* __restrict__ B2g, float* __restrict__ Cg)
{
    constexpr int NK      = KTOT / 32;
    constexpr int NSTAGE  = 3;
    constexpr int LDA     = 36;                         // floats
    constexpr int ABYTES  = 128 * LDA * 4;              // 18432
    constexpr int BN      = DUAL ? 64 : 128;            // CTA N width
    constexpr int NT      = DUAL ? 4 : 8;               // n8-tiles per warp
    constexpr int WNW     = 8 * NT;                     // warp N width
    constexpr int LDN     = DUAL ? 72 : 136;            // [k][n] stride, modes>=2
    constexpr int BBYTES  = (MODE <= 1) ? BN * LDA * 4 : 32 * LDN * 4;
    constexpr int STAGE   = ABYTES + BBYTES * (DUAL ? 2 : 1);
    constexpr bool CVT_A  = (MODE == 0 || MODE == 2);   // raw-fp32 A needs cvt
    constexpr int LDB_G   = (MODE == 0) ? HIDDEN : SHARED_FF; // modes 0/1 only

    extern __shared__ char smem_buf[];
    const uint32_t sb0 = smem_u32(smem_buf);

    const int t   = threadIdx.x;
    const int wid = t >> 5, lid = t & 31;
    const int wm  = wid & 3, wn = wid >> 2;
    const int g   = lid >> 2, tg = lid & 3;
    const int bn  = blockIdx.x * BN, bm = blockIdx.y * 128;

    int Me = 0; const int* lst = nullptr; size_t bbase = 0;
    if constexpr (MODE >= 2) {
        int e = blockIdx.z;
        Me = g_cnt[e];
        if (bm >= Me) return;
        lst = g_list[e];
        bbase = (size_t)e * KTOT * 1024;
    }

    // A fill assignment: thread covers rows fr+32i (i=0..3), 16B slot fj
    const int fj = t & 7, fr = t >> 3;
    const float* arow[4];
#pragma unroll
    for (int i = 0; i < 4; i++) {
        int row = fr + 32 * i;
        if constexpr (MODE == 0)      arow[i] = Ag   + (size_t)(bm + row) * HIDDEN;
        else if constexpr (MODE == 1) arow[i] = g_H1 + (size_t)(bm + row) * SHARED_FF;
        else {
            int m = bm + row; if (m > Me - 1) m = Me - 1;
            int ent = lst[m];
            if constexpr (MODE == 2) arow[i] = Ag   + (size_t)(ent >> 1) * HIDDEN;
            else                     arow[i] = g_Hx + (size_t)ent * MOE_FF;
        }
    }

    // ---- pipelined fill of one stage ----
    auto fill = [&](int kc) {
        const int k0 = kc * 32;
        const uint32_t sa = sb0 + (uint32_t)((kc % NSTAGE) * STAGE);
#pragma unroll
        for (int i = 0; i < 4; i++)
            CP_ASYNC16(sa + (uint32_t)((fr + 32 * i) * (LDA * 4) + fj * 16),
                       arow[i] + k0 + fj * 4);
        if constexpr (MODE <= 1) {
            // [n][k] rows: BN/32 rows per thread
#pragma unroll
            for (int i = 0; i < BN / 32; i++) {
                int row = fr + 32 * i;
                CP_ASYNC16(sa + ABYTES + (uint32_t)(row * (LDA * 4) + fj * 16),
                           Bg + (size_t)(bn + row) * LDB_G + k0 + fj * 4);
                if constexpr (DUAL)
                    CP_ASYNC16(sa + ABYTES + BBYTES + (uint32_t)(row * (LDA * 4) + fj * 16),
                               B2g + (size_t)(bn + row) * LDB_G + k0 + fj * 4);
            }
        } else {
            // [k][n]: 32 k-rows x BN floats; coalesced 16B chunks
            const int kk = t >> 3, n4 = t & 7;
            const float* src = Bg + bbase + (size_t)(k0 + kk) * 1024 + bn;
#pragma unroll
            for (int j = 0; j < BN / 32; j++) {
                int slot = n4 + 8 * j;
                CP_ASYNC16(sa + ABYTES + (uint32_t)(kk * (LDN * 4) + slot * 16),
                           src + slot * 4);
            }
            if constexpr (DUAL) {
                const float* src2 = src + 512;   // up-projection columns
#pragma unroll
                for (int j = 0; j < BN / 32; j++) {
                    int slot = n4 + 8 * j;
                    CP_ASYNC16(sa + ABYTES + BBYTES + (uint32_t)(kk * (LDN * 4) + slot * 16),
                               src2 + slot * 4);
                }
            }
        }
    };

    // ---- fragment loaders ----
    auto frag_a = [&](const float* As, int ks, uint32_t a[2][4]) {
        const int k = ks * 8;
#pragma unroll
        for (int mt = 0; mt < 2; mt++) {
            int r0 = (wm * 32 + mt * 16 + g) * LDA + k + tg;
            float a0 = As[r0], a1 = As[r0 + 8 * LDA];
            float a2 = As[r0 + 4], a3 = As[r0 + 8 * LDA + 4];
            if constexpr (CVT_A) {
                a0 = to_tf32(a0); a1 = to_tf32(a1);
                a2 = to_tf32(a2); a3 = to_tf32(a3);
            }
            a[mt][0] = __float_as_uint(a0); a[mt][1] = __float_as_uint(a1);
            a[mt][2] = __float_as_uint(a2); a[mt][3] = __float_as_uint(a3);
        }
    };
    auto frag_b = [&](const float* Bs, int ks, uint32_t b[NT][2]) {
        const int k = ks * 8;
#pragma unroll
        for (int nt = 0; nt < NT; nt++) {
            const int n = wn * WNW + nt * 8 + g;
            float v0, v1;
            if constexpr (MODE <= 1) {
                int n0 = n * LDA + k + tg;
                v0 = Bs[n0]; v1 = Bs[n0 + 4];
            } else {
                int n0 = (k + tg) * LDN + n;
                v0 = Bs[n0]; v1 = Bs[n0 + 4 * LDN];
            }
            b[nt][0] = __float_as_uint(to_tf32(v0));
            b[nt][1] = __float_as_uint(to_tf32(v1));
        }
    };

    float acc [2][NT][4];
    float acc2[DUAL ? 2 : 1][DUAL ? NT : 1][DUAL ? 4 : 1];
#pragma unroll
    for (int mt = 0; mt < 2; mt++)
#pragma unroll
        for (int nt = 0; nt < NT; nt++)
#pragma unroll
            for (int q = 0; q < 4; q++) {
                acc[mt][nt][q] = 0.f;
                if constexpr (DUAL) acc2[mt][nt][q] = 0.f;
            }

    // prologue: fill stages 0..NSTAGE-2
#pragma unroll
    for (int s = 0; s < NSTAGE - 1; s++) { fill(s); CP_COMMIT(); }

    for (int kc = 0; kc < NK; kc++) {
        if (kc + NSTAGE - 1 < NK) { fill(kc + NSTAGE - 1); CP_COMMIT(); }
        int last_issued = kc + NSTAGE - 1;
        if (last_issued > NK - 1) last_issued = NK - 1;
        const int pend = last_issued - kc;   // groups newer than fill(kc)
        if (pend >= 2)      CP_WAIT(2);
        else if (pend == 1) CP_WAIT(1);
        else                CP_WAIT(0);
        __syncthreads();

        const char* st = smem_buf + (kc % NSTAGE) * STAGE;
        const float* As  = (const float*)st;
        const float* Bs  = (const float*)(st + ABYTES);
        const float* B2s = (const float*)(st + ABYTES + BBYTES);

#pragma unroll
        for (int ks = 0; ks < 4; ks++) {
            uint32_t a[2][4], b[NT][2];
            frag_a(As, ks, a);
            frag_b(Bs, ks, b);
#pragma unroll
            for (int mt = 0; mt < 2; mt++)
#pragma unroll
                for (int nt = 0; nt < NT; nt++)
                    mma8(acc[mt][nt], a[mt], b[nt]);
            if constexpr (DUAL) {
                uint32_t b2[NT][2];
                frag_b(B2s, ks, b2);
#pragma unroll
                for (int mt = 0; mt < 2; mt++)
#pragma unroll
                    for (int nt = 0; nt < NT; nt++)
                        mma8(acc2[mt][nt], a[mt], b2[nt]);
            }
        }
        __syncthreads();
    }

    // ---- epilogue ----
#pragma unroll
    for (int mt = 0; mt < 2; mt++) {
#pragma unroll
        for (int ro = 0; ro < 2; ro++) {
            int m = bm + wm * 32 + mt * 16 + g + ro * 8;
            bool wr = true; float scale = 1.f; float* rp = nullptr;
            if constexpr (MODE == 0) {
                rp = g_H1 + (size_t)m * SHARED_FF;
            } else if constexpr (MODE == 1) {
                rp = Cg + (size_t)m * HIDDEN;
                scale = g_sig[m];
            } else {
                wr = (m < Me);
                int ent = lst[wr ? m : 0];
                if constexpr (MODE == 2) rp = g_Hx + (size_t)ent * MOE_FF;
                else { rp = g_partial + (size_t)ent * HIDDEN; scale = g_wts[ent]; }
            }
            if (wr) {
#pragma unroll
                for (int nt = 0; nt < NT; nt++) {
                    int col = bn + wn * WNW + nt * 8 + 2 * tg;
                    float x0 = acc[mt][nt][ro * 2 + 0];
                    float x1 = acc[mt][nt][ro * 2 + 1];
                    float2 o;
                    if constexpr (DUAL) {
                        // pre-round intermediates to tf32 so consumer skips cvt
                        o.x = to_tf32(silu_f(x0) * acc2[mt][nt][ro * 2 + 0]);
                        o.y = to_tf32(silu_f(x1) * acc2[mt][nt][ro * 2 + 1]);
                    } else {
                        o.x = x0 * scale;
                        o.y = x1 * scale;
                    }
                    *(float2*)(rp + col) = o;
                }
            }
        }
    }
}

// out += partial[2n] + partial[2n+1]
__global__ void k_combine(float* __restrict__ out) {
    int idx = blockIdx.x * blockDim.x + threadIdx.x;
    const int W = HIDDEN / 4;
    int n = idx / W;
    int c = idx - n * W;
    float4* o = (float4*)out;
    const float4* p = (const float4*)g_partial;
    float4 v  = o[idx];
    float4 p0 = p[(size_t)(2 * n) * W + c];
    float4 p1 = p[(size_t)(2 * n + 1) * W + c];
    v.x += p0.x + p1.x; v.y += p0.y + p1.y;
    v.z += p0.z + p1.z; v.w += p0.w + p1.w;
    o[idx] = v;
}

// ---------------- launch ----------------------------------------------------
extern "C" void kernel_launch(void* const* d_in, const int* in_sizes, int n_in,
                              void* d_out, int out_size) {
    const float* x    = (const float*)d_in[0];
    const float* gw   = (const float*)d_in[1];
    const float* wgu  = (const float*)d_in[2];
    const float* wdn  = (const float*)d_in[3];
    const float* swg  = (const float*)d_in[4];
    const float* swu  = (const float*)d_in[5];
    const float* swd  = (const float*)d_in[6];
    const float* sgw  = (const float*)d_in[7];
    float* out = (float*)d_out;

    // smem: dual = 3*(18432+2*9216) = 110592
    //       mode1 = 3*(18432+128*36*4) = 110592 ; mode3 = 3*(18432+32*136*4) = 107520
    const int SM_DUAL = 3 * (18432 + 2 * 9216);
    const int SM_M1   = 3 * (18432 + 128 * 36 * 4);
    const int SM_M3   = 3 * (18432 + 32 * 136 * 4);
    static bool init_done = false;
    static cudaStream_t s_exp;
    static cudaEvent_t ev_fork, ev_join;
    if (!init_done) {
        cudaFuncSetAttribute(k_mma<HIDDEN,    true,  0>, cudaFuncAttributeMaxDynamicSharedMemorySize, SM_DUAL);
        cudaFuncSetAttribute(k_mma<SHARED_FF, false, 1>, cudaFuncAttributeMaxDynamicSharedMemorySize, SM_M1);
        cudaFuncSetAttribute(k_mma<HIDDEN,    true,  2>, cudaFuncAttributeMaxDynamicSharedMemorySize, SM_DUAL);
        cudaFuncSetAttribute(k_mma<MOE_FF,    false, 3>, cudaFuncAttributeMaxDynamicSharedMemorySize, SM_M3);
        cudaStreamCreateWithFlags(&s_exp, cudaStreamNonBlocking);
        cudaEventCreateWithFlags(&ev_fork, cudaEventDisableTiming);
        cudaEventCreateWithFlags(&ev_join, cudaEventDisableTiming);
        init_done = true;
    }

    k_zero_cnt<<<1, 32>>>();
    k_router<<<NTOK, 128>>>(x, gw, sgw);

    // fork: expert chain on s_exp, shared chain on the launch stream
    cudaEventRecord(ev_fork, 0);
    cudaStreamWaitEvent(s_exp, ev_fork, 0);

    // expert gemm1: per-expert [Me x 512] dual, K=1024  (CTA 128x64)
    k_mma<HIDDEN, true, 2><<<dim3(MOE_FF / 64, NTOK / 128, NE), 256, SM_DUAL, s_exp>>>(
        x, wgu, nullptr, nullptr);
    // expert gemm2: per-expert [Me x 1024], K=512       (CTA 128x128)
    k_mma<MOE_FF, false, 3><<<dim3(HIDDEN / 128, NTOK / 128, NE), 256, SM_M3, s_exp>>>(
        nullptr, wdn, nullptr, nullptr);
    cudaEventRecord(ev_join, s_exp);

    // shared gemm1: [2048 x 2816] dual (gate, up), K=1024  (CTA 128x64)
    k_mma<HIDDEN, true, 0><<<dim3(SHARED_FF / 64, NTOK / 128), 256, SM_DUAL>>>(
        x, swg, swu, nullptr);
    // shared gemm2: [2048 x 1024], K=2816                  (CTA 128x128)
    k_mma<SHARED_FF, false, 1><<<dim3(HIDDEN / 128, NTOK / 128), 256, SM_M1>>>(
        nullptr, swd, nullptr, out);

    // join: combine needs both chains
    cudaStreamWaitEvent(0, ev_join, 0);
    k_combine<<<(NTOK * HIDDEN / 4) / 256, 256>>>(out);
}

// round 11
// speedup vs baseline: 1.1459x; 1.1459x over previous
#include <cuda_runtime.h>
#include <cstdint>

#define HIDDEN    1024
#define MOE_FF    512
#define SHARED_FF 2816
#define NE        16
#define NTOK      2048
#define NENT      (2*NTOK)

// ---------------- scratch (device globals; no allocation allowed) ----------
__device__ float g_H1[NTOK * SHARED_FF];     // shared-expert hidden (tf32-rounded)
__device__ float g_Hx[NENT * MOE_FF];        // expert hidden per entry (tf32-rounded)
__device__ float g_partial[NENT * HIDDEN];   // weighted expert out per entry
__device__ int   g_list[NE][NTOK];           // entry id (2n+k) per expert bucket
__device__ int   g_cnt[NE];
__device__ float g_wts[NENT];                // renormalized router weight per entry
__device__ float g_sig[NTOK];                // shared-expert sigmoid gate

__device__ __forceinline__ float silu_f(float v) { return v / (1.f + __expf(-v)); }
__device__ __forceinline__ float to_tf32(float x) {
    float y; asm("cvt.rna.tf32.f32 %0, %1;" : "=f"(y) : "f"(x)); return y;
}

// m16n8k8 TF32 HMMA (generic PTX — valid on target sm_103)
__device__ __forceinline__ void mma8(float* c, const uint32_t* a, const uint32_t* b) {
    asm volatile(
        "mma.sync.aligned.m16n8k8.row.col.f32.tf32.tf32.f32 "
        "{%0,%1,%2,%3}, {%4,%5,%6,%7}, {%8,%9}, {%0,%1,%2,%3};"
        : "+f"(c[0]), "+f"(c[1]), "+f"(c[2]), "+f"(c[3])
        : "r"(a[0]), "r"(a[1]), "r"(a[2]), "r"(a[3]), "r"(b[0]), "r"(b[1]));
}

__device__ __forceinline__ uint32_t smem_u32(const void* p) {
    uint32_t a;
    asm("{ .reg .u64 t; cvta.to.shared.u64 t, %1; cvt.u32.u64 %0, t; }" : "=r"(a) : "l"(p));
    return a;
}
#define CP_ASYNC16(dst, src) \
    asm volatile("cp.async.cg.shared.global [%0], [%1], 16;" :: "r"(dst), "l"(src))
#define CP_COMMIT() asm volatile("cp.async.commit_group;" ::: "memory")
#define CP_WAIT(n)  asm volatile("cp.async.wait_group %0;" :: "n"(n) : "memory")

// ---------------- misc ------------------------------------------------------
__global__ void k_zero_cnt() {
    if (threadIdx.x < NE) g_cnt[threadIdx.x] = 0;
}

// ---------------- router: logits -> top2 -> renorm weights + buckets --------
__global__ void k_router(const float* __restrict__ x,
                         const float* __restrict__ gw,
                         const float* __restrict__ sgw) {
    int n = blockIdx.x;
    int t = threadIdx.x;
    float xv[8];
#pragma unroll
    for (int i = 0; i < 8; i++) xv[i] = x[n * HIDDEN + t + i * 128];

    __shared__ float red[17 * 4];
    for (int e = 0; e < 17; e++) {
        const float* wr = (e < 16) ? (gw + e * HIDDEN) : sgw;
        float s = 0.f;
#pragma unroll
        for (int i = 0; i < 8; i++) s += xv[i] * wr[t + i * 128];
#pragma unroll
        for (int o = 16; o; o >>= 1) s += __shfl_xor_sync(0xffffffffu, s, o);
        if ((t & 31) == 0) red[e * 4 + (t >> 5)] = s;
    }
    __syncthreads();
    if (t == 0) {
        float lg[17];
        for (int e = 0; e < 17; e++)
            lg[e] = red[e * 4] + red[e * 4 + 1] + red[e * 4 + 2] + red[e * 4 + 3];
        int i0 = 0;
        for (int e = 1; e < 16; e++) if (lg[e] > lg[i0]) i0 = e;
        int i1 = -1;
        for (int e = 0; e < 16; e++) {
            if (e == i0) continue;
            if (i1 < 0 || lg[e] > lg[i1]) i1 = e;
        }
        float m  = lg[i0];
        float e0 = expf(lg[i0] - m);
        float e1 = expf(lg[i1] - m);
        float inv = 1.f / (e0 + e1);
        g_wts[2 * n]     = e0 * inv;
        g_wts[2 * n + 1] = e1 * inv;
        int p0 = atomicAdd(&g_cnt[i0], 1); g_list[i0][p0] = 2 * n;
        int p1 = atomicAdd(&g_cnt[i1], 1); g_list[i1][p1] = 2 * n + 1;
        g_sig[n] = 1.f / (1.f + expf(-lg[16]));
    }
}

// ---------------- TF32 HMMA GEMM, 3-stage cp.async ring, 1 barrier/chunk ----
// CTA 128xBN, 8 warps 4Mx2N. DUAL modes (0,2) and MODE1: BN=64, warp 32x32;
// MODE1 additionally register-double-buffers fragments. MODE3: BN=128,
// warp 32x64. A smem [m][k] LDA=36; B smem modes 0/1 [n][k] LDA=36,
// modes 2/3 [k][n] LDN=BN+8. All fragment LDS conflict-free.
// Loop structure (single __syncthreads per K-chunk):
//   wait(own groups thru fill(kc)) ; barrier ; fill(kc+2) ; compute(kc)
// fill(kc+2) targets stage (kc-1)%3 — freed by the barrier (all warps past
// compute(kc-1)).
template<int KTOT, bool DUAL, int MODE, int BN>
__global__ void __launch_bounds__(256, 2)
k_mma(const float* __restrict__ Ag, const float* __restrict__ Bg,
      const float* __restrict__ B2g, float* __restrict__ Cg)
{
    constexpr int NK      = KTOT / 32;
    constexpr int NSTAGE  = 3;
    constexpr int LDA     = 36;                         // floats
    constexpr int ABYTES  = 128 * LDA * 4;              // 18432
    constexpr int NT      = BN / 16;                    // n8-tiles per warp
    constexpr int WNW     = BN / 2;                     // warp N width
    constexpr int LDN     = BN + 8;                     // [k][n] stride, modes>=2
    constexpr int BBYTES  = (MODE <= 1) ? BN * LDA * 4 : 32 * LDN * 4;
    constexpr int STAGE   = ABYTES + BBYTES * (DUAL ? 2 : 1);
    constexpr bool CVT_A  = (MODE == 0 || MODE == 2);   // raw-fp32 A needs cvt
    constexpr int LDB_G   = (MODE == 0) ? HIDDEN : SHARED_FF; // modes 0/1 only
    constexpr bool FDB    = (!DUAL && BN == 64);        // frag double-buffer

    extern __shared__ char smem_buf[];
    const uint32_t sb0 = smem_u32(smem_buf);

    const int t   = threadIdx.x;
    const int wid = t >> 5, lid = t & 31;
    const int wm  = wid & 3, wn = wid >> 2;
    const int g   = lid >> 2, tg = lid & 3;
    const int bn  = blockIdx.x * BN, bm = blockIdx.y * 128;

    int Me = 0; const int* lst = nullptr; size_t bbase = 0;
    if constexpr (MODE >= 2) {
        int e = blockIdx.z;
        Me = g_cnt[e];
        if (bm >= Me) return;
        lst = g_list[e];
        bbase = (size_t)e * KTOT * 1024;
    }

    // A fill assignment: thread covers rows fr+32i (i=0..3), 16B slot fj
    const int fj = t & 7, fr = t >> 3;
    const float* arow[4];
#pragma unroll
    for (int i = 0; i < 4; i++) {
        int row = fr + 32 * i;
        if constexpr (MODE == 0)      arow[i] = Ag   + (size_t)(bm + row) * HIDDEN;
        else if constexpr (MODE == 1) arow[i] = g_H1 + (size_t)(bm + row) * SHARED_FF;
        else {
            int m = bm + row; if (m > Me - 1) m = Me - 1;
            int ent = lst[m];
            if constexpr (MODE == 2) arow[i] = Ag   + (size_t)(ent >> 1) * HIDDEN;
            else                     arow[i] = g_Hx + (size_t)ent * MOE_FF;
        }
    }

    // ---- pipelined fill of one stage ----
    auto fill = [&](int kc) {
        const int k0 = kc * 32;
        const uint32_t sa = sb0 + (uint32_t)((kc % NSTAGE) * STAGE);
#pragma unroll
        for (int i = 0; i < 4; i++)
            CP_ASYNC16(sa + (uint32_t)((fr + 32 * i) * (LDA * 4) + fj * 16),
                       arow[i] + k0 + fj * 4);
        if constexpr (MODE <= 1) {
            // [n][k] rows: BN/32 rows per thread
#pragma unroll
            for (int i = 0; i < BN / 32; i++) {
                int row = fr + 32 * i;
                CP_ASYNC16(sa + ABYTES + (uint32_t)(row * (LDA * 4) + fj * 16),
                           Bg + (size_t)(bn + row) * LDB_G + k0 + fj * 4);
                if constexpr (DUAL)
                    CP_ASYNC16(sa + ABYTES + BBYTES + (uint32_t)(row * (LDA * 4) + fj * 16),
                               B2g + (size_t)(bn + row) * LDB_G + k0 + fj * 4);
            }
        } else {
            // [k][n]: 32 k-rows x BN floats; coalesced 16B chunks
            const int kk = t >> 3, n4 = t & 7;
            const float* src = Bg + bbase + (size_t)(k0 + kk) * 1024 + bn;
#pragma unroll
            for (int j = 0; j < BN / 32; j++) {
                int slot = n4 + 8 * j;
                CP_ASYNC16(sa + ABYTES + (uint32_t)(kk * (LDN * 4) + slot * 16),
                           src + slot * 4);
            }
            if constexpr (DUAL) {
                const float* src2 = src + 512;   // up-projection columns
#pragma unroll
                for (int j = 0; j < BN / 32; j++) {
                    int slot = n4 + 8 * j;
                    CP_ASYNC16(sa + ABYTES + BBYTES + (uint32_t)(kk * (LDN * 4) + slot * 16),
                               src2 + slot * 4);
                }
            }
        }
    };

    // ---- fragment loaders ----
    auto frag_a = [&](const float* As, int ks, uint32_t a[2][4]) {
        const int k = ks * 8;
#pragma unroll
        for (int mt = 0; mt < 2; mt++) {
            int r0 = (wm * 32 + mt * 16 + g) * LDA + k + tg;
            float a0 = As[r0], a1 = As[r0 + 8 * LDA];
            float a2 = As[r0 + 4], a3 = As[r0 + 8 * LDA + 4];
            if constexpr (CVT_A) {
                a0 = to_tf32(a0); a1 = to_tf32(a1);
                a2 = to_tf32(a2); a3 = to_tf32(a3);
            }
            a[mt][0] = __float_as_uint(a0); a[mt][1] = __float_as_uint(a1);
            a[mt][2] = __float_as_uint(a2); a[mt][3] = __float_as_uint(a3);
        }
    };
    auto frag_b = [&](const float* Bs, int ks, uint32_t b[NT][2]) {
        const int k = ks * 8;
#pragma unroll
        for (int nt = 0; nt < NT; nt++) {
            const int n = wn * WNW + nt * 8 + g;
            float v0, v1;
            if constexpr (MODE <= 1) {
                int n0 = n * LDA + k + tg;
                v0 = Bs[n0]; v1 = Bs[n0 + 4];
            } else {
                int n0 = (k + tg) * LDN + n;
                v0 = Bs[n0]; v1 = Bs[n0 + 4 * LDN];
            }
            b[nt][0] = __float_as_uint(to_tf32(v0));
            b[nt][1] = __float_as_uint(to_tf32(v1));
        }
    };

    float acc [2][NT][4];
    float acc2[DUAL ? 2 : 1][DUAL ? NT : 1][DUAL ? 4 : 1];
#pragma unroll
    for (int mt = 0; mt < 2; mt++)
#pragma unroll
        for (int nt = 0; nt < NT; nt++)
#pragma unroll
            for (int q = 0; q < 4; q++) {
                acc[mt][nt][q] = 0.f;
                if constexpr (DUAL) acc2[mt][nt][q] = 0.f;
            }

    // prologue: fill stages 0..NSTAGE-2
#pragma unroll
    for (int s = 0; s < NSTAGE - 1; s++) { fill(s); CP_COMMIT(); }

    for (int kc = 0; kc < NK; kc++) {
        // wait for own groups through fill(kc); barrier publishes all threads'
        if (kc < NK - 1) CP_WAIT(1);
        else             CP_WAIT(0);
        __syncthreads();
        // fill(kc+2) targets stage (kc-1)%3 — free now (barrier passed)
        if (kc + NSTAGE - 1 < NK) { fill(kc + NSTAGE - 1); CP_COMMIT(); }

        const char* st = smem_buf + (kc % NSTAGE) * STAGE;
        const float* As  = (const float*)st;
        const float* Bs  = (const float*)(st + ABYTES);
        const float* B2s = (const float*)(st + ABYTES + BBYTES);

        if constexpr (FDB) {
            // register double-buffered fragments: LDS of ks+1 overlaps MMAs of ks
            uint32_t aP[2][2][4], bP[2][NT][2];
            frag_a(As, 0, aP[0]); frag_b(Bs, 0, bP[0]);
#pragma unroll
            for (int ks = 0; ks < 4; ks++) {
                const int cur = ks & 1, nxt = cur ^ 1;
                if (ks < 3) { frag_a(As, ks + 1, aP[nxt]); frag_b(Bs, ks + 1, bP[nxt]); }
#pragma unroll
                for (int mt = 0; mt < 2; mt++)
#pragma unroll
                    for (int nt = 0; nt < NT; nt++)
                        mma8(acc[mt][nt], aP[cur][mt], bP[cur][nt]);
            }
        } else {
#pragma unroll
            for (int ks = 0; ks < 4; ks++) {
                uint32_t a[2][4], b[NT][2];
                frag_a(As, ks, a);
                frag_b(Bs, ks, b);
#pragma unroll
                for (int mt = 0; mt < 2; mt++)
#pragma unroll
                    for (int nt = 0; nt < NT; nt++)
                        mma8(acc[mt][nt], a[mt], b[nt]);
                if constexpr (DUAL) {
                    uint32_t b2[NT][2];
                    frag_b(B2s, ks, b2);
#pragma unroll
                    for (int mt = 0; mt < 2; mt++)
#pragma unroll
                        for (int nt = 0; nt < NT; nt++)
                            mma8(acc2[mt][nt], a[mt], b2[nt]);
                }
            }
        }
    }

    // ---- epilogue ----
#pragma unroll
    for (int mt = 0; mt < 2; mt++) {
#pragma unroll
        for (int ro = 0; ro < 2; ro++) {
            int m = bm + wm * 32 + mt * 16 + g + ro * 8;
            bool wr = true; float scale = 1.f; float* rp = nullptr;
            if constexpr (MODE == 0) {
                rp = g_H1 + (size_t)m * SHARED_FF;
            } else if constexpr (MODE == 1) {
                rp = Cg + (size_t)m * HIDDEN;
                scale = g_sig[m];
            } else {
                wr = (m < Me);
                int ent = lst[wr ? m : 0];
                if constexpr (MODE == 2) rp = g_Hx + (size_t)ent * MOE_FF;
                else { rp = g_partial + (size_t)ent * HIDDEN; scale = g_wts[ent]; }
            }
            if (wr) {
#pragma unroll
                for (int nt = 0; nt < NT; nt++) {
                    int col = bn + wn * WNW + nt * 8 + 2 * tg;
                    float x0 = acc[mt][nt][ro * 2 + 0];
                    float x1 = acc[mt][nt][ro * 2 + 1];
                    float2 o;
                    if constexpr (DUAL) {
                        // pre-round intermediates to tf32 so consumer skips cvt
                        o.x = to_tf32(silu_f(x0) * acc2[mt][nt][ro * 2 + 0]);
                        o.y = to_tf32(silu_f(x1) * acc2[mt][nt][ro * 2 + 1]);
                    } else {
                        o.x = x0 * scale;
                        o.y = x1 * scale;
                    }
                    *(float2*)(rp + col) = o;
                }
            }
        }
    }
}

// out += partial[2n] + partial[2n+1]
__global__ void k_combine(float* __restrict__ out) {
    int idx = blockIdx.x * blockDim.x + threadIdx.x;
    const int W = HIDDEN / 4;
    int n = idx / W;
    int c = idx - n * W;
    float4* o = (float4*)out;
    const float4* p = (const float4*)g_partial;
    float4 v  = o[idx];
    float4 p0 = p[(size_t)(2 * n) * W + c];
    float4 p1 = p[(size_t)(2 * n + 1) * W + c];
    v.x += p0.x + p1.x; v.y += p0.y + p1.y;
    v.z += p0.z + p1.z; v.w += p0.w + p1.w;
    o[idx] = v;
}

// ---------------- launch ----------------------------------------------------
extern "C" void kernel_launch(void* const* d_in, const int* in_sizes, int n_in,
                              void* d_out, int out_size) {
    const float* x    = (const float*)d_in[0];
    const float* gw   = (const float*)d_in[1];
    const float* wgu  = (const float*)d_in[2];
    const float* wdn  = (const float*)d_in[3];
    const float* swg  = (const float*)d_in[4];
    const float* swu  = (const float*)d_in[5];
    const float* swd  = (const float*)d_in[6];
    const float* sgw  = (const float*)d_in[7];
    float* out = (float*)d_out;

    // smem: dual = 3*(18432+2*9216)=110592 ; mode1 = 3*(18432+9216)=82944
    //       mode3 (BN=128, LDN=136) = 3*(18432+17408)=107520
    const int SM_DUAL = 3 * (18432 + 2 * 9216);
    const int SM_M1   = 3 * (18432 + 9216);
    const int SM_M3   = 3 * (18432 + 32 * 136 * 4);
    static bool init_done = false;
    static cudaStream_t s_exp;
    static cudaEvent_t ev_fork, ev_rt, ev_join;
    if (!init_done) {
        cudaFuncSetAttribute(k_mma<HIDDEN,    true,  0, 64 >, cudaFuncAttributeMaxDynamicSharedMemorySize, SM_DUAL);
        cudaFuncSetAttribute(k_mma<SHARED_FF, false, 1, 64 >, cudaFuncAttributeMaxDynamicSharedMemorySize, SM_M1);
        cudaFuncSetAttribute(k_mma<HIDDEN,    true,  2, 64 >, cudaFuncAttributeMaxDynamicSharedMemorySize, SM_DUAL);
        cudaFuncSetAttribute(k_mma<MOE_FF,    false, 3, 128>, cudaFuncAttributeMaxDynamicSharedMemorySize, SM_M3);
        cudaStreamCreateWithFlags(&s_exp, cudaStreamNonBlocking);
        cudaEventCreateWithFlags(&ev_fork, cudaEventDisableTiming);
        cudaEventCreateWithFlags(&ev_rt,   cudaEventDisableTiming);
        cudaEventCreateWithFlags(&ev_join, cudaEventDisableTiming);
        init_done = true;
    }

    // fork expert stream from the launch stream (required for graph capture)
    cudaEventRecord(ev_fork, 0);
    cudaStreamWaitEvent(s_exp, ev_fork, 0);

    // expert stream: router + expert chain (MODE0 does not need the router)
    k_zero_cnt<<<1, 32, 0, s_exp>>>();
    k_router<<<NTOK, 128, 0, s_exp>>>(x, gw, sgw);
    cudaEventRecord(ev_rt, s_exp);   // g_sig ready (needed by MODE1 epilogue)

    // expert gemm1: per-expert [Me x 512] dual, K=1024  (CTA 128x64)
    k_mma<HIDDEN, true, 2, 64><<<dim3(MOE_FF / 64, NTOK / 128, NE), 256, SM_DUAL, s_exp>>>(
        x, wgu, nullptr, nullptr);
    // expert gemm2: per-expert [Me x 1024], K=512       (CTA 128x128)
    k_mma<MOE_FF, false, 3, 128><<<dim3(HIDDEN / 128, NTOK / 128, NE), 256, SM_M3, s_exp>>>(
        nullptr, wdn, nullptr, nullptr);
    cudaEventRecord(ev_join, s_exp);

    // main stream: shared gemm1 starts immediately (no router dependency)
    k_mma<HIDDEN, true, 0, 64><<<dim3(SHARED_FF / 64, NTOK / 128), 256, SM_DUAL>>>(
        x, swg, swu, nullptr);
    // shared gemm2 needs g_sig (router) — wait costs nothing, router is long done
    cudaStreamWaitEvent(0, ev_rt, 0);
    k_mma<SHARED_FF, false, 1, 64><<<dim3(HIDDEN / 64, NTOK / 128), 256, SM_M1>>>(
        nullptr, swd, nullptr, out);

    // join: combine needs both chains
    cudaStreamWaitEvent(0, ev_join, 0);
    k_combine<<<(NTOK * HIDDEN / 4) / 256, 256>>>(out);
}